// round 12
// baseline (speedup 1.0000x reference)
#include <cuda_runtime.h>
#include <math.h>

// Problem constants (B=2, T=16, N=1024, D=3)
#define BT       32
#define NPTS     1024
#define TPB      256
#define NQ       16                   // candidate lane-split groups
#define POWN     8                    // owned points per thread
#define OGRP     (TPB / NQ)           // 16 owned groups
#define OWNED    (OGRP * POWN)        // 128 owned points per block
#define OCH      (NPTS / OWNED)       // 8 owned chunks per (batch, direction)
#define CPAIRS   (NPTS / 2)           // 512 packed candidate pairs in smem
#define ITERS    (CPAIRS / NQ)        // 32 pair-iterations per thread
#define NBLOCKS  (BT * 2 * OCH)       // 512
#define EPS      1e-6f

__device__ float        g_partials[NBLOCKS];
__device__ unsigned int g_count = 0;

// ---- packed f32x2 helpers (sm_100+; ptxas never auto-fuses) ----
__device__ __forceinline__ unsigned long long pack2(float a, float b) {
    unsigned long long r;
    asm("mov.b64 %0, {%1, %2};" : "=l"(r) : "f"(a), "f"(b));
    return r;
}
__device__ __forceinline__ unsigned long long fma2(unsigned long long a,
                                                   unsigned long long b,
                                                   unsigned long long c) {
    unsigned long long d;
    asm("fma.rn.f32x2 %0, %1, %2, %3;" : "=l"(d) : "l"(a), "l"(b), "l"(c));
    return d;
}
__device__ __forceinline__ void unpack2(unsigned long long v, float& lo, float& hi) {
    asm("mov.b64 {%0, %1}, %2;" : "=f"(lo), "=f"(hi) : "l"(v));
}

__global__ void __launch_bounds__(TPB, 4)
chamfer_kernel(const float* __restrict__ x, const float* __restrict__ y,
               float* __restrict__ out) {
    // Candidate pairs, split halves in ONE array (16B lane stride, conflict-free):
    //   s_c[p]          = {x0, x1, y0, y1}
    //   s_c[CPAIRS + p] = {z0, z1, -h0, -h1}
    __shared__ float4 s_c[2 * CPAIRS];          // 16KB
    __shared__ float  s_own[OWNED * 3];         // raw owned coords (1.5KB)
    __shared__ float  warp_sums[TPB / 32];
    __shared__ bool   sh_last;

    const int bt    = blockIdx.x >> 4;          // batch (32)
    const int dir   = (blockIdx.x >> 3) & 1;    // 0: owned=x, cand=y; 1: reverse
    const int chunk = blockIdx.x & 7;           // owned chunk (8)
    const int tid   = threadIdx.x;

    const float* xb = x + (size_t)bt * NPTS * 3;
    const float* yb = y + (size_t)bt * NPTS * 3;
    const float* ownp = dir ? yb : xb;
    const float* cndp = dir ? xb : yb;

    // ---- stage owned chunk raw via coalesced float4 (128 pts = 96 float4) ----
    if (tid < OWNED * 3 / 4) {
        const float4 v = ((const float4*)(ownp + (size_t)chunk * OWNED * 3))[tid];
        ((float4*)s_own)[tid] = v;
    }

    // ---- stage ALL 1024 candidates: 3 LDG.128 -> repack -> 4 STS.128 ----
    {
        // thread t handles pairs 2t, 2t+1 (points 4t..4t+3)
        const float4* cf = (const float4*)cndp;
        float4 v0 = cf[3 * tid + 0];
        float4 v1 = cf[3 * tid + 1];
        float4 v2 = cf[3 * tid + 2];
        // pair 0: points (v0.x,v0.y,v0.z) and (v0.w,v1.x,v1.y)
        {
            float nh0 = -0.5f * (v0.x * v0.x + v0.y * v0.y + v0.z * v0.z);
            float nh1 = -0.5f * (v0.w * v0.w + v1.x * v1.x + v1.y * v1.y);
            s_c[2 * tid]          = make_float4(v0.x, v0.w, v0.y, v1.x);
            s_c[CPAIRS + 2 * tid] = make_float4(v0.z, v1.y, nh0, nh1);
        }
        // pair 1: points (v1.z,v1.w,v2.x) and (v2.y,v2.z,v2.w)
        {
            float nh0 = -0.5f * (v1.z * v1.z + v1.w * v1.w + v2.x * v2.x);
            float nh1 = -0.5f * (v2.y * v2.y + v2.z * v2.z + v2.w * v2.w);
            s_c[2 * tid + 1]          = make_float4(v1.z, v2.y, v1.w, v2.z);
            s_c[CPAIRS + 2 * tid + 1] = make_float4(v2.x, v2.w, nh0, nh1);
        }
    }
    __syncthreads();

    // ---- owned register tile: 8 points from smem, splatted for f32x2 ----
    const int q = tid & (NQ - 1);               // candidate group 0..15
    const int g = tid >> 4;                     // owned group 0..15
    unsigned long long Ax2[POWN], Ay2[POWN], Az2[POWN];
#pragma unroll
    for (int k = 0; k < POWN; ++k) {
        const int o = g + OGRP * k;             // local owned index
        float a0 = s_own[3 * o + 0], a1 = s_own[3 * o + 1], a2 = s_own[3 * o + 2];
        Ax2[k] = pack2(a0, a0);
        Ay2[k] = pack2(a1, a1);
        Az2[k] = pack2(a2, a2);
    }

    float m[POWN];
#pragma unroll
    for (int k = 0; k < POWN; ++k) m[k] = -INFINITY;

    // ---- hot loop: 2x LDS.128 per candidate pair; unroll 4 keeps the
    //      candidate double-buffer inside the 64-reg budget ----
    const ulonglong2* pa = (const ulonglong2*)s_c + q;
#pragma unroll 4
    for (int i = 0; i < ITERS; ++i) {
        ulonglong2 va = pa[NQ * i];             // (x0,x1),(y0,y1)
        ulonglong2 vb = pa[NQ * i + CPAIRS];    // (z0,z1),(-h0,-h1)
#pragma unroll
        for (int k = 0; k < POWN; ++k) {
            unsigned long long t = fma2(Az2[k], vb.x, vb.y);
            t = fma2(Ay2[k], va.y, t);
            t = fma2(Ax2[k], va.x, t);
            float lo, hi;
            unpack2(t, lo, hi);
            m[k] = fmaxf(m[k], fmaxf(lo, hi));  // merged tree, 1 accumulator
        }
    }

    // ---- combine the 16 candidate groups (within warp), epilogue h from smem ----
    float contrib = 0.0f;
#pragma unroll
    for (int k = 0; k < POWN; ++k) {
        float mm = m[k];
#pragma unroll
        for (int off = 1; off < NQ; off <<= 1)
            mm = fmaxf(mm, __shfl_xor_sync(0xFFFFFFFFu, mm, off));
        if (q == 0) {
            const int o = g + OGRP * k;
            float a0 = s_own[3 * o + 0], a1 = s_own[3 * o + 1], a2 = s_own[3 * o + 2];
            float h = 0.5f * (a0 * a0 + a1 * a1 + a2 * a2);
            // min_i sq = 2*(h - mm); clamp, dist = sqrt(EPS + sq)
            float sq = fmaxf(2.0f * (h - mm), 0.0f);
            contrib += sqrtf(EPS + sq);
        }
    }

    // ---- block reduction (fixed order -> deterministic) ----
#pragma unroll
    for (int off = 16; off > 0; off >>= 1)
        contrib += __shfl_down_sync(0xFFFFFFFFu, contrib, off);
    if ((tid & 31) == 0) warp_sums[tid >> 5] = contrib;
    __syncthreads();

    if (tid == 0) {
        float s = 0.0f;
#pragma unroll
        for (int w = 0; w < TPB / 32; ++w) s += warp_sums[w];
        g_partials[blockIdx.x] = s;
        __threadfence();
        unsigned int done = atomicAdd(&g_count, 1u);
        sh_last = (done == NBLOCKS - 1);
    }
    __syncthreads();
    if (!sh_last) return;

    // ---- fused final reduction in the last block (fixed order) ----
    __threadfence();
    float v = __ldcg(&g_partials[tid]) + __ldcg(&g_partials[tid + TPB]);
#pragma unroll
    for (int off = 16; off > 0; off >>= 1)
        v += __shfl_down_sync(0xFFFFFFFFu, v, off);
    if ((tid & 31) == 0) warp_sums[tid >> 5] = v;
    __syncthreads();
    if (tid == 0) {
        float s = 0.0f;
#pragma unroll
        for (int w = 0; w < TPB / 32; ++w) s += warp_sums[w];
        out[0]  = s * (1.0f / (float)(BT * NPTS));
        g_count = 0u;                           // reset for next graph replay
    }
}

extern "C" void kernel_launch(void* const* d_in, const int* in_sizes, int n_in,
                              void* d_out, int out_size) {
    const float* x = (const float*)d_in[0];
    const float* y = (const float*)d_in[1];
    float* out = (float*)d_out;
    (void)in_sizes; (void)n_in; (void)out_size;

    chamfer_kernel<<<NBLOCKS, TPB>>>(x, y, out);
}

// round 15
// speedup vs baseline: 1.0850x; 1.0850x over previous
#include <cuda_runtime.h>
#include <math.h>

// Problem constants (B=2, T=16, N=1024, D=3)
#define BT       32
#define NPTS     1024
#define TPB      256
#define NQ       16                   // candidate lane-split groups
#define OGRP     16                   // owned groups (tid>>4)
#define OWNED    128                  // owned points per chunk
#define OCH      8                    // chunks per (batch, direction)
#define CPAIRS   (NPTS / 2)           // 512 packed candidate pairs in smem
#define ITERS    (CPAIRS / NQ)        // 32 pair-iterations per thread
#define UNITS    (BT * 2 * OCH)       // 512 owned-chunk units
#define FULLB    444                  // full-size blocks (= 3 blocks/SM * 148 SMs)
#define NBLOCKS  (FULLB + 2 * (UNITS - FULLB))  // 444 + 136 = 580
#define EPS      1e-6f

__device__ float        g_partials[NBLOCKS];
__device__ unsigned int g_count = 0;

// ---- packed f32x2 helpers (sm_100+; ptxas never auto-fuses) ----
__device__ __forceinline__ unsigned long long pack2(float a, float b) {
    unsigned long long r;
    asm("mov.b64 %0, {%1, %2};" : "=l"(r) : "f"(a), "f"(b));
    return r;
}
__device__ __forceinline__ unsigned long long fma2(unsigned long long a,
                                                   unsigned long long b,
                                                   unsigned long long c) {
    unsigned long long d;
    asm("fma.rn.f32x2 %0, %1, %2, %3;" : "=l"(d) : "l"(a), "l"(b), "l"(c));
    return d;
}
__device__ __forceinline__ void unpack2(unsigned long long v, float& lo, float& hi) {
    asm("mov.b64 {%0, %1}, %2;" : "=f"(lo), "=f"(hi) : "l"(v));
}

// Hot path templated on owned-points-per-thread. obase selects which half of
// the staged chunk a half-block processes. Returns this thread's contrib
// (nonzero only on q==0 lanes).
template <int PN>
__device__ __forceinline__ float hot_compute(const ulonglong2* pa,
                                             const ulonglong2* pb,
                                             const float* s_own,
                                             int q, int g, int obase) {
    unsigned long long Ax2[PN], Ay2[PN], Az2[PN];
#pragma unroll
    for (int k = 0; k < PN; ++k) {
        const int o = obase + g + OGRP * k;
        float a0 = s_own[3 * o + 0], a1 = s_own[3 * o + 1], a2 = s_own[3 * o + 2];
        Ax2[k] = pack2(a0, a0);
        Ay2[k] = pack2(a1, a1);
        Az2[k] = pack2(a2, a2);
    }
    float m[PN];
#pragma unroll
    for (int k = 0; k < PN; ++k) m[k] = -INFINITY;

#pragma unroll 8
    for (int i = 0; i < ITERS; ++i) {
        ulonglong2 va = pa[NQ * i];             // (x0,x1),(y0,y1)
        ulonglong2 vb = pb[NQ * i];             // (z0,z1),(-h0,-h1)
#pragma unroll
        for (int k = 0; k < PN; ++k) {
            unsigned long long t = fma2(Az2[k], vb.x, vb.y);
            t = fma2(Ay2[k], va.y, t);
            t = fma2(Ax2[k], va.x, t);
            float lo, hi;
            unpack2(t, lo, hi);
            m[k] = fmaxf(m[k], fmaxf(lo, hi));
        }
    }

    float contrib = 0.0f;
#pragma unroll
    for (int k = 0; k < PN; ++k) {
        float mm = m[k];
#pragma unroll
        for (int off = 1; off < NQ; off <<= 1)
            mm = fmaxf(mm, __shfl_xor_sync(0xFFFFFFFFu, mm, off));
        if (q == 0) {
            const int o = obase + g + OGRP * k;
            float a0 = s_own[3 * o + 0], a1 = s_own[3 * o + 1], a2 = s_own[3 * o + 2];
            float h = 0.5f * (a0 * a0 + a1 * a1 + a2 * a2);
            float sq = fmaxf(2.0f * (h - mm), 0.0f);   // min_i dist^2, clamped
            contrib += sqrtf(EPS + sq);
        }
    }
    return contrib;
}

__global__ void __launch_bounds__(TPB, 3)
chamfer_kernel(const float* __restrict__ x, const float* __restrict__ y,
               float* __restrict__ out) {
    // Candidate pairs, split halves (16B lane stride, conflict-free):
    //   s_ca[p] = {x0, x1, y0, y1}   s_cb[p] = {z0, z1, -h0, -h1}
    __shared__ float4 s_ca[CPAIRS];             // 8KB
    __shared__ float4 s_cb[CPAIRS];             // 8KB
    __shared__ float  s_own[OWNED * 3];         // raw owned coords (1.5KB)
    __shared__ float  warp_sums[TPB / 32];
    __shared__ bool   sh_last;

    const int bid = blockIdx.x;
    // Unit mapping: blocks <FULLB take one full chunk-unit; blocks >=FULLB come
    // in pairs, each taking half the owned points of units FULLB..UNITS-1.
    const int u    = (bid < FULLB) ? bid : (FULLB + ((bid - FULLB) >> 1));
    const int half = (bid < FULLB) ? 0 : ((bid - FULLB) & 1);

    const int bt    = u >> 4;                   // batch (32)
    const int dir   = (u >> 3) & 1;             // 0: owned=x, cand=y; 1: reverse
    const int chunk = u & 7;                    // owned chunk (8)
    const int tid   = threadIdx.x;

    const float* xb = x + (size_t)bt * NPTS * 3;
    const float* yb = y + (size_t)bt * NPTS * 3;
    const float* ownp = dir ? yb : xb;
    const float* cndp = dir ? xb : yb;

    // ---- stage owned chunk raw via coalesced float4 (128 pts = 96 float4) ----
    if (tid < OWNED * 3 / 4) {
        const float4 v = ((const float4*)(ownp + (size_t)chunk * OWNED * 3))[tid];
        ((float4*)s_own)[tid] = v;
    }

    // ---- stage ALL 1024 candidates: 3 LDG.128 -> repack -> 4 STS.128 ----
    {
        // thread t handles pairs 2t, 2t+1 (points 4t..4t+3)
        const float4* cf = (const float4*)cndp;
        float4 v0 = cf[3 * tid + 0];
        float4 v1 = cf[3 * tid + 1];
        float4 v2 = cf[3 * tid + 2];
        // pair 0: points (v0.x,v0.y,v0.z) and (v0.w,v1.x,v1.y)
        {
            float nh0 = -0.5f * (v0.x * v0.x + v0.y * v0.y + v0.z * v0.z);
            float nh1 = -0.5f * (v0.w * v0.w + v1.x * v1.x + v1.y * v1.y);
            s_ca[2 * tid] = make_float4(v0.x, v0.w, v0.y, v1.x);
            s_cb[2 * tid] = make_float4(v0.z, v1.y, nh0, nh1);
        }
        // pair 1: points (v1.z,v1.w,v2.x) and (v2.y,v2.z,v2.w)
        {
            float nh0 = -0.5f * (v1.z * v1.z + v1.w * v1.w + v2.x * v2.x);
            float nh1 = -0.5f * (v2.y * v2.y + v2.z * v2.z + v2.w * v2.w);
            s_ca[2 * tid + 1] = make_float4(v1.z, v2.y, v1.w, v2.z);
            s_cb[2 * tid + 1] = make_float4(v2.x, v2.w, nh0, nh1);
        }
    }
    __syncthreads();

    const int q = tid & (NQ - 1);               // candidate group 0..15
    const int g = tid >> 4;                     // owned group 0..15
    const ulonglong2* pa = (const ulonglong2*)s_ca + q;
    const ulonglong2* pb = (const ulonglong2*)s_cb + q;

    float contrib;
    if (bid < FULLB) {
        contrib = hot_compute<8>(pa, pb, s_own, q, g, 0);
    } else {
        contrib = hot_compute<4>(pa, pb, s_own, q, g, half * (OWNED / 2));
    }

    // ---- block reduction (fixed order -> deterministic) ----
#pragma unroll
    for (int off = 16; off > 0; off >>= 1)
        contrib += __shfl_down_sync(0xFFFFFFFFu, contrib, off);
    if ((tid & 31) == 0) warp_sums[tid >> 5] = contrib;
    __syncthreads();

    if (tid == 0) {
        float s = 0.0f;
#pragma unroll
        for (int w = 0; w < TPB / 32; ++w) s += warp_sums[w];
        g_partials[bid] = s;
        __threadfence();
        unsigned int done = atomicAdd(&g_count, 1u);
        sh_last = (done == NBLOCKS - 1);
    }
    __syncthreads();
    if (!sh_last) return;

    // ---- fused final reduction in the last block (fixed order) ----
    __threadfence();
    float v = __ldcg(&g_partials[tid]) + __ldcg(&g_partials[tid + TPB]);
    if (tid < NBLOCKS - 2 * TPB)                // remaining 68 entries
        v += __ldcg(&g_partials[tid + 2 * TPB]);
#pragma unroll
    for (int off = 16; off > 0; off >>= 1)
        v += __shfl_down_sync(0xFFFFFFFFu, v, off);
    if ((tid & 31) == 0) warp_sums[tid >> 5] = v;
    __syncthreads();
    if (tid == 0) {
        float s = 0.0f;
#pragma unroll
        for (int w = 0; w < TPB / 32; ++w) s += warp_sums[w];
        out[0]  = s * (1.0f / (float)(BT * NPTS));
        g_count = 0u;                           // reset for next graph replay
    }
}

extern "C" void kernel_launch(void* const* d_in, const int* in_sizes, int n_in,
                              void* d_out, int out_size) {
    const float* x = (const float*)d_in[0];
    const float* y = (const float*)d_in[1];
    float* out = (float*)d_out;
    (void)in_sizes; (void)n_in; (void)out_size;

    chamfer_kernel<<<NBLOCKS, TPB>>>(x, y, out);
}